// round 1
// baseline (speedup 1.0000x reference)
#include <cuda_runtime.h>

// Problem constants
#define BB   256      // batch
#define TT   512      // timesteps (only last one matters)
#define DIN  64
#define HIDN 64
#define NBAS 10
#define KDIM (DIN*NBAS)   // 640
#define NCLS 2

// Kernel config
#define RPB   2                 // batch rows per block
#define NBLK  (BB/RPB)          // 128 blocks
#define NTHR  256
#define SPLIT 16                // split-k groups
#define KPER  (KDIM/SPLIT)      // 40 k-iters per thread

__device__ __forceinline__ float fast_tanh(float y) {
    // tanh(y) = 1 - 2/(exp(2y)+1); safe at +/-inf of expf
    float e = __expf(2.0f * y);
    return 1.0f - __fdividef(2.0f, e + 1.0f);
}
__device__ __forceinline__ float fast_sigmoid(float y) {
    return __fdividef(1.0f, 1.0f + __expf(-y));
}

__global__ __launch_bounds__(NTHR) void node_rnn_fused_kernel(
    const float* __restrict__ x,
    const float* __restrict__ c0, const float* __restrict__ w0, const float* __restrict__ C0,
    const float* __restrict__ c1, const float* __restrict__ w1, const float* __restrict__ C1,
    const float* __restrict__ c2, const float* __restrict__ w2, const float* __restrict__ C2,
    const float* __restrict__ Whead, const float* __restrict__ bhead,
    float* __restrict__ out)
{
    __shared__ float s_in [RPB][HIDN];
    __shared__ float s_phi[RPB][KDIM];
    __shared__ float s_red[SPLIT][RPB][HIDN];
    __shared__ float s_out[RPB][HIDN];
    __shared__ float s_c[3][NBAS], s_iw[3][NBAS];

    const int tid = threadIdx.x;

    // Load centers / inverse widths for all 3 stages
    if (tid < NBAS)            { s_c[0][tid]      = c0[tid];      s_iw[0][tid]      = __frcp_rn(w0[tid]); }
    else if (tid < 2*NBAS)     { int k = tid-NBAS;   s_c[1][k] = c1[k]; s_iw[1][k] = __frcp_rn(w1[k]); }
    else if (tid < 3*NBAS)     { int k = tid-2*NBAS; s_c[2][k] = c2[k]; s_iw[2][k] = __frcp_rn(w2[k]); }

    // Load last-timestep input rows for this block
    const int r0 = blockIdx.x * RPB;
    if (tid < RPB * DIN) {
        int r = tid >> 6, i = tid & 63;
        s_in[r][i] = x[(size_t)(r0 + r) * (TT * DIN) + (size_t)(TT - 1) * DIN + i];
    }
    __syncthreads();

    const int q = tid & 15;     // output quad: columns 4q..4q+3
    const int g = tid >> 4;     // split-k group 0..15
    const float* Cs[3] = { C0, C1, C2 };

    #pragma unroll 1
    for (int stage = 0; stage < 3; ++stage) {
        // ---- phi expansion: phi[r][i*NB+k] = tanh((in[r][i]-c_k)/w_k) ----
        if (tid < RPB * HIDN) {
            int r = tid >> 6, i = tid & 63;
            float xv = s_in[r][i];
            #pragma unroll
            for (int k = 0; k < NBAS; ++k)
                s_phi[r][i * NBAS + k] = fast_tanh((xv - s_c[stage][k]) * s_iw[stage][k]);
        }
        __syncthreads();

        // ---- split-k GEMM: out[r][o] = sum_kk phi[r][kk] * C[kk][o] ----
        float acc[RPB][4];
        #pragma unroll
        for (int r = 0; r < RPB; ++r)
            acc[r][0] = acc[r][1] = acc[r][2] = acc[r][3] = 0.0f;

        const float* __restrict__ C = Cs[stage];
        const int kk0 = g * KPER;
        #pragma unroll 8
        for (int kk = kk0; kk < kk0 + KPER; ++kk) {
            float4 c4 = *reinterpret_cast<const float4*>(C + (size_t)kk * HIDN + 4 * q);
            #pragma unroll
            for (int r = 0; r < RPB; ++r) {
                float p = s_phi[r][kk];
                acc[r][0] = fmaf(p, c4.x, acc[r][0]);
                acc[r][1] = fmaf(p, c4.y, acc[r][1]);
                acc[r][2] = fmaf(p, c4.z, acc[r][2]);
                acc[r][3] = fmaf(p, c4.w, acc[r][3]);
            }
        }
        #pragma unroll
        for (int r = 0; r < RPB; ++r)
            *reinterpret_cast<float4*>(&s_red[g][r][4 * q]) =
                make_float4(acc[r][0], acc[r][1], acc[r][2], acc[r][3]);
        __syncthreads();

        // ---- reduce split-k partials + activation ----
        if (tid < RPB * HIDN) {
            int r = tid >> 6, o = tid & 63;
            float s = 0.0f;
            #pragma unroll
            for (int gg = 0; gg < SPLIT; ++gg) s += s_red[gg][r][o];
            s_out[r][o] = (stage == 0) ? s : fast_sigmoid(s);
        }
        __syncthreads();

        // chain: stage output becomes next stage input
        if (stage < 2 && tid < RPB * HIDN) {
            int r = tid >> 6, o = tid & 63;
            s_in[r][o] = s_out[r][o];
        }
        __syncthreads();
    }

    // ---- head: logits[r][c] = phi3[r] . W[:,c] + b[c]  (tiny GEMV) ----
    if (tid < RPB * NCLS) {
        int r = tid / NCLS, c = tid % NCLS;
        float s = bhead[c];
        #pragma unroll
        for (int o = 0; o < HIDN; ++o)
            s = fmaf(s_out[r][o], Whead[o * NCLS + c], s);
        out[(r0 + r) * NCLS + c] = s;
    }
}

extern "C" void kernel_launch(void* const* d_in, const int* in_sizes, int n_in,
                              void* d_out, int out_size) {
    (void)in_sizes; (void)n_in; (void)out_size;
    const float* x  = (const float*)d_in[0];
    const float* c0 = (const float*)d_in[1];
    const float* w0 = (const float*)d_in[2];
    const float* C0 = (const float*)d_in[3];
    const float* c1 = (const float*)d_in[4];
    const float* w1 = (const float*)d_in[5];
    const float* C1 = (const float*)d_in[6];
    const float* c2 = (const float*)d_in[7];
    const float* w2 = (const float*)d_in[8];
    const float* C2 = (const float*)d_in[9];
    const float* W  = (const float*)d_in[10];
    const float* b  = (const float*)d_in[11];
    float* out = (float*)d_out;

    node_rnn_fused_kernel<<<NBLK, NTHR>>>(x, c0, w0, C0, c1, w1, C1,
                                          c2, w2, C2, W, b, out);
}

// round 3
// speedup vs baseline: 1.8861x; 1.8861x over previous
#include <cuda_runtime.h>

// Problem constants
#define BB   256      // batch
#define TT   512      // timesteps (only last one matters)
#define DIN  64
#define HIDN 64
#define NBAS 10
#define KDIM (DIN*NBAS)   // 640
#define NCLS 2

// Kernel config
#define RPB   2                 // batch rows per block
#define NBLK  (BB/RPB)          // 128 blocks
#define NTHR  512
#define SPLIT 32                // split-k groups
#define KPER  (KDIM/SPLIT)      // 20 k-iters per thread

__device__ __forceinline__ float fast_tanh(float y) {
    // tanh(y) = 1 - 2/(exp(2y)+1); safe at +/-inf of expf
    float e = __expf(2.0f * y);
    return 1.0f - __fdividef(2.0f, e + 1.0f);
}
__device__ __forceinline__ float fast_sigmoid(float y) {
    return __fdividef(1.0f, 1.0f + __expf(-y));
}

__global__ __launch_bounds__(NTHR) void node_rnn_fused_kernel(
    const float* __restrict__ x,
    const float* __restrict__ c0, const float* __restrict__ w0, const float* __restrict__ C0,
    const float* __restrict__ c1, const float* __restrict__ w1, const float* __restrict__ C1,
    const float* __restrict__ c2, const float* __restrict__ w2, const float* __restrict__ C2,
    const float* __restrict__ Whead, const float* __restrict__ bhead,
    float* __restrict__ out)
{
    __shared__ float s_val[RPB][HIDN];            // stage input / output
    __shared__ float s_phi[RPB][KDIM];
    __shared__ float s_red[SPLIT][RPB][HIDN];
    __shared__ float s_c[3][NBAS], s_iw[3][NBAS];
    __shared__ float s_W[HIDN * NCLS];
    __shared__ float s_b[NCLS];

    const int tid = threadIdx.x;
    const int r0  = blockIdx.x * RPB;

    // --- startup loads (all independent; high MLP) ---
    if (tid < NBAS)        { s_c[0][tid]      = c0[tid];      s_iw[0][tid]      = __frcp_rn(w0[tid]); }
    else if (tid < 2*NBAS) { int k = tid-NBAS;   s_c[1][k] = c1[k]; s_iw[1][k] = __frcp_rn(w1[k]); }
    else if (tid < 3*NBAS) { int k = tid-2*NBAS; s_c[2][k] = c2[k]; s_iw[2][k] = __frcp_rn(w2[k]); }

    if (tid >= 128 && tid < 128 + HIDN * NCLS) s_W[tid - 128] = Whead[tid - 128];
    if (tid >= 384 && tid < 384 + NCLS)        s_b[tid - 384] = bhead[tid - 384];

    if (tid >= 256 && tid < 256 + RPB * DIN) {
        int t = tid - 256;
        int r = t >> 6, i = t & 63;
        s_val[r][i] = x[(size_t)(r0 + r) * (TT * DIN) + (size_t)(TT - 1) * DIN + i];
    }
    __syncthreads();

    const int q = tid & 15;     // output quad: columns 4q..4q+3
    const int g = tid >> 4;     // split-k group 0..31
    const float* Cs[3] = { C0, C1, C2 };
    const int kk0 = g * KPER;

    #pragma unroll 1
    for (int stage = 0; stage < 3; ++stage) {
        // ---- front-batched coefficient loads: independent of phi, MLP=KPER ----
        const float* __restrict__ C = Cs[stage];
        float4 cv[KPER];
        #pragma unroll
        for (int j = 0; j < KPER; ++j)
            cv[j] = *reinterpret_cast<const float4*>(C + (size_t)(kk0 + j) * HIDN + 4 * q);

        // ---- phi expansion (overlaps with in-flight coefficient loads) ----
        if (tid < RPB * HIDN) {
            int r = tid >> 6, i = tid & 63;
            float xv = s_val[r][i];
            #pragma unroll
            for (int k = 0; k < NBAS; ++k)
                s_phi[r][i * NBAS + k] = fast_tanh((xv - s_c[stage][k]) * s_iw[stage][k]);
        }
        __syncthreads();

        // ---- split-k GEMM from registers + smem phi ----
        float acc[RPB][4];
        #pragma unroll
        for (int r = 0; r < RPB; ++r)
            acc[r][0] = acc[r][1] = acc[r][2] = acc[r][3] = 0.0f;

        #pragma unroll
        for (int j = 0; j < KPER; ++j) {
            float4 c4 = cv[j];
            #pragma unroll
            for (int r = 0; r < RPB; ++r) {
                float p = s_phi[r][kk0 + j];
                acc[r][0] = fmaf(p, c4.x, acc[r][0]);
                acc[r][1] = fmaf(p, c4.y, acc[r][1]);
                acc[r][2] = fmaf(p, c4.z, acc[r][2]);
                acc[r][3] = fmaf(p, c4.w, acc[r][3]);
            }
        }
        #pragma unroll
        for (int r = 0; r < RPB; ++r)
            *reinterpret_cast<float4*>(&s_red[g][r][4 * q]) =
                make_float4(acc[r][0], acc[r][1], acc[r][2], acc[r][3]);
        __syncthreads();

        // ---- reduce split-k partials + activation; result -> s_val ----
        if (tid < RPB * HIDN) {
            int r = tid >> 6, o = tid & 63;
            float s = 0.0f;
            #pragma unroll
            for (int gg = 0; gg < SPLIT; ++gg) s += s_red[gg][r][o];
            s_val[r][o] = (stage == 0) ? s : fast_sigmoid(s);
        }
        __syncthreads();
    }

    // ---- head: logits[r][c] = phi3[r] . W[:,c] + b[c]  (tiny GEMV) ----
    if (tid < RPB * NCLS) {
        int r = tid / NCLS, c = tid % NCLS;
        float s = s_b[c];
        #pragma unroll
        for (int o = 0; o < HIDN; ++o)
            s = fmaf(s_val[r][o], s_W[o * NCLS + c], s);
        out[(r0 + r) * NCLS + c] = s;
    }
}

extern "C" void kernel_launch(void* const* d_in, const int* in_sizes, int n_in,
                              void* d_out, int out_size) {
    (void)in_sizes; (void)n_in; (void)out_size;
    const float* x  = (const float*)d_in[0];
    const float* c0 = (const float*)d_in[1];
    const float* w0 = (const float*)d_in[2];
    const float* C0 = (const float*)d_in[3];
    const float* c1 = (const float*)d_in[4];
    const float* w1 = (const float*)d_in[5];
    const float* C1 = (const float*)d_in[6];
    const float* c2 = (const float*)d_in[7];
    const float* w2 = (const float*)d_in[8];
    const float* C2 = (const float*)d_in[9];
    const float* W  = (const float*)d_in[10];
    const float* b  = (const float*)d_in[11];
    float* out = (float*)d_out;

    node_rnn_fused_kernel<<<NBLK, NTHR>>>(x, c0, w0, C0, c1, w1, C1,
                                          c2, w2, C2, W, b, out);
}

// round 6
// speedup vs baseline: 2.1108x; 1.1191x over previous
#include <cuda_runtime.h>

// Problem constants
#define BB   256      // batch
#define TT   512      // timesteps (only last one matters)
#define DIN  64
#define HIDN 64
#define NBAS 10
#define KDIM (DIN*NBAS)   // 640
#define NCLS 2

// Kernel config
#define RPB   2                 // batch rows per block
#define NBLK  (BB/RPB)          // 128 blocks
#define NTHR  512
#define SPLIT 32                // split-k groups
#define KPER  (KDIM/SPLIT)      // 20 k-iters per thread
#define REDW  68                // padded s_red row (bank-conflict-free, 16B-aligned)

__device__ __forceinline__ float fast_tanh(float y) {
    float e = __expf(2.0f * y);
    return 1.0f - __fdividef(2.0f, e + 1.0f);
}
__device__ __forceinline__ float fast_sigmoid(float y) {
    return __fdividef(1.0f, 1.0f + __expf(-y));
}

__global__ __launch_bounds__(NTHR) void node_rnn_fused_kernel(
    const float* __restrict__ x,
    const float* __restrict__ c0, const float* __restrict__ w0, const float* __restrict__ C0,
    const float* __restrict__ c1, const float* __restrict__ w1, const float* __restrict__ C1,
    const float* __restrict__ c2, const float* __restrict__ w2, const float* __restrict__ C2,
    const float* __restrict__ Whead, const float* __restrict__ bhead,
    float* __restrict__ out)
{
    __shared__ float s_val[RPB][HIDN];                 // stage input / output
    __shared__ float s_phi[RPB][KDIM];
    __shared__ float s_red[SPLIT][RPB][REDW];          // padded: conflict-free reduce
    __shared__ float s_c[3][NBAS], s_iw[3][NBAS];
    __shared__ float s_W[HIDN * NCLS];
    __shared__ float s_b[NCLS];

    const int tid = threadIdx.x;
    const int r0  = blockIdx.x * RPB;

    // --- startup loads (independent, high MLP) ---
    if (tid < NBAS)        { s_c[0][tid]      = c0[tid];      s_iw[0][tid]      = __frcp_rn(w0[tid]); }
    else if (tid < 2*NBAS) { int k = tid-NBAS;   s_c[1][k] = c1[k]; s_iw[1][k] = __frcp_rn(w1[k]); }
    else if (tid < 3*NBAS) { int k = tid-2*NBAS; s_c[2][k] = c2[k]; s_iw[2][k] = __frcp_rn(w2[k]); }

    if (tid >= 128 && tid < 128 + HIDN * NCLS) s_W[tid - 128] = Whead[tid - 128];
    if (tid >= 384 && tid < 384 + NCLS)        s_b[tid - 384] = bhead[tid - 384];

    if (tid >= 256 && tid < 256 + RPB * DIN) {
        int t = tid - 256;
        int r = t >> 6, i = t & 63;
        s_val[r][i] = x[(size_t)(r0 + r) * (TT * DIN) + (size_t)(TT - 1) * DIN + i];
    }

    const int q = tid & 15;     // output quad: columns 4q..4q+3
    const int g = tid >> 4;     // split-k group 0..31
    const int kk0 = g * KPER;

    // reduce assignment: 4 threads per output, each sums 8 interleaved groups
    const int o_idx = tid >> 2;          // 0..127
    const int part  = tid & 3;
    const int rr    = o_idx >> 6;
    const int oo    = o_idx & 63;

    const float* Cs[3] = { C0, C1, C2 };

    // ---- stage-0 coefficient loads (front-batched) ----
    float4 cv[KPER];
    #pragma unroll
    for (int j = 0; j < KPER; ++j)
        cv[j] = *reinterpret_cast<const float4*>(C0 + (size_t)(kk0 + j) * HIDN + 4 * q);

    __syncthreads();   // s_val (x rows) + consts ready

    // ---- stage-0 phi, spread across ALL threads ----
    #pragma unroll
    for (int it = tid; it < RPB * KDIM; it += NTHR) {
        int r = it / KDIM, rem = it - r * KDIM;
        int i = rem / NBAS, k = rem - i * NBAS;
        s_phi[r][rem] = fast_tanh((s_val[r][i] - s_c[0][k]) * s_iw[0][k]);
    }
    __syncthreads();

    #pragma unroll 1
    for (int stage = 0; stage < 3; ++stage) {
        // ---- split-k GEMM: registers (coeffs) x smem (phi, float4) ----
        float acc[RPB][4];
        #pragma unroll
        for (int r = 0; r < RPB; ++r)
            acc[r][0] = acc[r][1] = acc[r][2] = acc[r][3] = 0.0f;

        #pragma unroll
        for (int jj = 0; jj < KPER / 4; ++jj) {
            float4 p0 = *reinterpret_cast<const float4*>(&s_phi[0][kk0 + 4 * jj]);
            float4 p1 = *reinterpret_cast<const float4*>(&s_phi[1][kk0 + 4 * jj]);
            #pragma unroll
            for (int e = 0; e < 4; ++e) {
                float4 c4 = cv[4 * jj + e];
                float pa = (e == 0) ? p0.x : (e == 1) ? p0.y : (e == 2) ? p0.z : p0.w;
                float pb = (e == 0) ? p1.x : (e == 1) ? p1.y : (e == 2) ? p1.z : p1.w;
                acc[0][0] = fmaf(pa, c4.x, acc[0][0]);
                acc[0][1] = fmaf(pa, c4.y, acc[0][1]);
                acc[0][2] = fmaf(pa, c4.z, acc[0][2]);
                acc[0][3] = fmaf(pa, c4.w, acc[0][3]);
                acc[1][0] = fmaf(pb, c4.x, acc[1][0]);
                acc[1][1] = fmaf(pb, c4.y, acc[1][1]);
                acc[1][2] = fmaf(pb, c4.z, acc[1][2]);
                acc[1][3] = fmaf(pb, c4.w, acc[1][3]);
            }
        }

        // ---- prefetch NEXT stage's coefficients (cv regs now dead) ----
        if (stage < 2) {
            const float* __restrict__ Cn = Cs[stage + 1];
            #pragma unroll
            for (int j = 0; j < KPER; ++j)
                cv[j] = *reinterpret_cast<const float4*>(Cn + (size_t)(kk0 + j) * HIDN + 4 * q);
        }

        // ---- write partials ----
        #pragma unroll
        for (int r = 0; r < RPB; ++r)
            *reinterpret_cast<float4*>(&s_red[g][r][4 * q]) =
                make_float4(acc[r][0], acc[r][1], acc[r][2], acc[r][3]);
        __syncthreads();

        // ---- reduce (all threads: 4 per output, 8 partials each) + shuffle ----
        {
            float v = 0.0f;
            #pragma unroll
            for (int jj = 0; jj < 8; ++jj)
                v += s_red[part + 4 * jj][rr][oo];
            v += __shfl_xor_sync(0xffffffffu, v, 1);
            v += __shfl_xor_sync(0xffffffffu, v, 2);
            if (part == 0)
                s_val[rr][oo] = (stage == 0) ? v : fast_sigmoid(v);
        }
        __syncthreads();

        // ---- next stage phi (spread over all threads) ----
        if (stage < 2) {
            int st = stage + 1;
            #pragma unroll
            for (int it = tid; it < RPB * KDIM; it += NTHR) {
                int r = it / KDIM, rem = it - r * KDIM;
                int i = rem / NBAS, k = rem - i * NBAS;
                s_phi[r][rem] = fast_tanh((s_val[r][i] - s_c[st][k]) * s_iw[st][k]);
            }
            __syncthreads();
        }
    }

    // ---- head: logits[r][c] = phi3[r] . W[:,c] + b[c] ----
    if (tid < RPB * NCLS) {
        int r = tid / NCLS, c = tid % NCLS;
        float s = s_b[c];
        #pragma unroll
        for (int o = 0; o < HIDN; ++o)
            s = fmaf(s_val[r][o], s_W[o * NCLS + c], s);
        out[(r0 + r) * NCLS + c] = s;
    }
}

extern "C" void kernel_launch(void* const* d_in, const int* in_sizes, int n_in,
                              void* d_out, int out_size) {
    (void)in_sizes; (void)n_in; (void)out_size;
    const float* x  = (const float*)d_in[0];
    const float* c0 = (const float*)d_in[1];
    const float* w0 = (const float*)d_in[2];
    const float* C0 = (const float*)d_in[3];
    const float* c1 = (const float*)d_in[4];
    const float* w1 = (const float*)d_in[5];
    const float* C1 = (const float*)d_in[6];
    const float* c2 = (const float*)d_in[7];
    const float* w2 = (const float*)d_in[8];
    const float* C2 = (const float*)d_in[9];
    const float* W  = (const float*)d_in[10];
    const float* b  = (const float*)d_in[11];
    float* out = (float*)d_out;

    node_rnn_fused_kernel<<<NBLK, NTHR>>>(x, c0, w0, C0, c1, w1, C1,
                                          c2, w2, C2, W, b, out);
}